// round 10
// baseline (speedup 1.0000x reference)
#include <cuda_runtime.h>
#include <cuda_fp16.h>
#include <mma.h>
#include <cstdint>

using namespace nvcuda;

// PointTransformerLayer, raw mma.sync.m16n8k16. Tile = 128 rows = 8 pts x 16 nbrs.
// A_ext[128x128] = [nf | delta], B_ext[128x128] = [[Wal, Wpsi@Wga],[unused, -Wga]]
// D_lo = nf@Wal -> alpha = D_lo + b_al + delta ; gamma = fgc - D_hi
// out[p,d] = sum_k softmax_d(gamma[k,:])[d] * alpha[k,d]
// B fragments in registers across all tiles; gamma softmax on acc registers.

constexpr int DIM = 64;
constexpr int THREADS = 256;
constexpr int LDA = 136;  // halves: A_ext & Bt row stride
constexpr int LDW = 72;   // floats: wbuf/abuf stride
constexpr int LDF = 68;   // floats: A2 fgD stride

constexpr int RAWNF  = 0;       // 32768
constexpr int RAWFGC = 32768;   // 2048
constexpr int RAWPX  = 34816;   // 128
constexpr int RAWNX  = 34944;   // 1536
constexpr int AO     = 36864;   // 34816  A_ext fp16 [128][136]
constexpr int BTO    = 71680;   // 34816  Bt fp16 [128 n][136 k]
constexpr int WBO    = 106496;  // 36864  wbuf f32 [128][72]; wfgb overlay (A2)
constexpr int ABO    = 143360;  // 36864  abuf f32 [128][72]; fgD overlay (A2)
constexpr int FGCSO  = 180224;  // 2048
constexpr int BALO   = 182272;  // 256
constexpr int MCVO   = 182528;  // 1024
constexpr int CGO    = 183552;  // 256
constexpr int SMEM_BYTES = 183808;

__device__ __forceinline__ uint32_t s2u(const void* p) {
    uint32_t a;
    asm("{ .reg .u64 t; cvta.to.shared.u64 t, %1; cvt.u32.u64 %0, t; }" : "=r"(a) : "l"(p));
    return a;
}
__device__ __forceinline__ void cp16(unsigned dst, const void* src) {
    asm volatile("cp.async.cg.shared.global [%0], [%1], 16;\n" :: "r"(dst), "l"(src));
}
__device__ __forceinline__ void cp_commit() { asm volatile("cp.async.commit_group;\n"); }
template <int NN>
__device__ __forceinline__ void cp_wait() {
    asm volatile("cp.async.wait_group %0;\n" :: "n"(NN));
}
__device__ __forceinline__ void ldmx4(uint32_t* r, uint32_t addr) {
    asm volatile("ldmatrix.sync.aligned.m8n8.x4.shared.b16 {%0,%1,%2,%3}, [%4];"
                 : "=r"(r[0]), "=r"(r[1]), "=r"(r[2]), "=r"(r[3]) : "r"(addr));
}
__device__ __forceinline__ void mma16816(float* d, const uint32_t* a, const uint32_t* b) {
    asm volatile(
        "mma.sync.aligned.m16n8k16.row.col.f32.f16.f16.f32 "
        "{%0,%1,%2,%3}, {%4,%5,%6,%7}, {%8,%9}, {%0,%1,%2,%3};"
        : "+f"(d[0]), "+f"(d[1]), "+f"(d[2]), "+f"(d[3])
        : "r"(a[0]), "r"(a[1]), "r"(a[2]), "r"(a[3]), "r"(b[0]), "r"(b[1]));
}

__device__ __forceinline__ void prefetch_tile(char* sm, int tile, int tid,
                                              const float* __restrict__ pxyz,
                                              const float* __restrict__ nxyz,
                                              const float* __restrict__ nfeat,
                                              const float* __restrict__ fgc_src, int N)
{
    const long base = (long)tile * 8;
    const unsigned nf_a = s2u(sm + RAWNF), fg_a = s2u(sm + RAWFGC),
                   px_a = s2u(sm + RAWPX), nx_a = s2u(sm + RAWNX);
    const float* nsrc = nfeat + base * 1024;
    #pragma unroll
    for (int r = 0; r < 8; r++) { int i = tid + 256 * r; cp16(nf_a + i * 16, nsrc + i * 4); }
    if (tid < 128) cp16(fg_a + tid * 16, fgc_src + base * 64 + tid * 4);
    if (tid < 6)   cp16(px_a + tid * 16, pxyz + base * 3 + tid * 4);
    if (tid < 96)  cp16(nx_a + tid * 16, nxyz + base * 48 + tid * 4);
    cp_commit();
}

__device__ __forceinline__ void convert_tile(char* sm, int tid)
{
    const float4* rnf = (const float4*)(sm + RAWNF);
    __half* Ah = (__half*)(sm + AO);
    #pragma unroll
    for (int r = 0; r < 8; r++) {
        int i4 = tid + 256 * r;
        float4 v = rnf[i4];
        int e = i4 * 4, row = e >> 6, c = e & 63;
        __half2 h0 = __floats2half2_rn(v.x, v.y);
        __half2 h1 = __floats2half2_rn(v.z, v.w);
        *(uint2*)(Ah + row * LDA + c) = make_uint2(*(uint32_t*)&h0, *(uint32_t*)&h1);
    }
    {
        float* fs = (float*)(sm + FGCSO);
        const float* rf = (const float*)(sm + RAWFGC);
        fs[tid] = rf[tid];
        fs[tid + 256] = rf[tid + 256];
    }
    {
        const float* rpx = (const float*)(sm + RAWPX);
        const float* rnx = (const float*)(sm + RAWNX);
        const float* mcv = (const float*)(sm + MCVO);
        const int row = tid >> 1, h = tid & 1, p = row >> 4;
        const float dx = rpx[p * 3 + 0] - rnx[row * 3 + 0];
        const float dy = rpx[p * 3 + 1] - rnx[row * 3 + 1];
        const float dz = rpx[p * 3 + 2] - rnx[row * 3 + 2];
        #pragma unroll
        for (int i4 = 0; i4 < 8; i4++) {
            const int d = h * 32 + i4 * 4;
            float4 m0 = *(const float4*)(mcv + d);
            float4 m1 = *(const float4*)(mcv + 64 + d);
            float4 m2 = *(const float4*)(mcv + 128 + d);
            float4 cv = *(const float4*)(mcv + 192 + d);
            float v0 = fmaxf(fmaf(dx, m0.x, fmaf(dy, m1.x, fmaf(dz, m2.x, cv.x))), 0.f);
            float v1 = fmaxf(fmaf(dx, m0.y, fmaf(dy, m1.y, fmaf(dz, m2.y, cv.y))), 0.f);
            float v2 = fmaxf(fmaf(dx, m0.z, fmaf(dy, m1.z, fmaf(dz, m2.z, cv.z))), 0.f);
            float v3 = fmaxf(fmaf(dx, m0.w, fmaf(dy, m1.w, fmaf(dz, m2.w, cv.w))), 0.f);
            __half2 h0 = __floats2half2_rn(v0, v1);
            __half2 h1 = __floats2half2_rn(v2, v3);
            *(uint2*)(Ah + row * LDA + 64 + d) = make_uint2(*(uint32_t*)&h0, *(uint32_t*)&h1);
        }
    }
}

__global__ void __launch_bounds__(THREADS, 1)
pt_main(const float* __restrict__ pxyz,  const float* __restrict__ pfeat,
        const float* __restrict__ nxyz,  const float* __restrict__ nfeat,
        const float* __restrict__ Wphi,  const float* __restrict__ bphi,
        const float* __restrict__ Wpsi,  const float* __restrict__ bpsi,
        const float* __restrict__ Wal,   const float* __restrict__ bal,
        const float* __restrict__ Wga,   const float* __restrict__ bga,
        const float* __restrict__ Wd1,   const float* __restrict__ bd1,
        const float* __restrict__ Wd2,   const float* __restrict__ bd2,
        float* __restrict__ out, int N)
{
    extern __shared__ __align__(1024) char sm[];
    const int tid = threadIdx.x, lane = tid & 31, warp = tid >> 5;
    const int cg = warp >> 2, rg = warp & 3;
    const int bx = blockIdx.x, G = gridDim.x;
    const int ntiles = (N + 7) >> 3;
    const int numtt = (ntiles - bx + G - 1) / G;

    __half* bt   = (__half*)(sm + BTO);
    __half* wfgb = (__half*)(sm + WBO);
    float*  cgs  = (float*)(sm + CGO);

    // ---- Phase A: weight fusion ----
    {
        float* sWga  = (float*)(sm + 0);
        float* sWgaT = (float*)(sm + 16384);
        float* sWphi = (float*)(sm + 33792);
        float* sWpsi = (float*)(sm + 50176);
        #pragma unroll
        for (int m = 0; m < 16; m++) {
            int i = tid + 256 * m;
            sWga[i] = Wga[i]; sWphi[i] = Wphi[i]; sWpsi[i] = Wpsi[i];
        }
        __syncthreads();
        #pragma unroll
        for (int m = 0; m < 16; m++) {
            int i = tid + 256 * m; int e = i >> 6, d = i & 63;
            sWgaT[d * 68 + e] = sWga[e * 64 + d];
        }
        __syncthreads();
        #pragma unroll
        for (int m = 0; m < 16; m++) {
            int v = tid + 256 * m; int k = v >> 6, n = v & 63;
            bt[n * LDA + k]             = __float2half_rn(Wal[k * 64 + n]);
            bt[n * LDA + 64 + k]        = __float2half_rn(0.f);
            bt[(64 + n) * LDA + 64 + k] = __float2half_rn(-sWga[k * 64 + n]);
        }
        #pragma unroll
        for (int m = 0; m < 16; m++) {
            int v = tid + 256 * m; int k = v >> 6, n = v & 63;
            const float4* pa = (const float4*)(sWpsi + k * 64);
            const float4* pb = (const float4*)(sWphi + k * 64);
            const float4* pg = (const float4*)(sWgaT + n * 68);
            float s1 = 0.f, s2 = 0.f;
            #pragma unroll
            for (int e4 = 0; e4 < 16; e4++) {
                float4 a = pa[e4], bb = pb[e4], g = pg[e4];
                s1 = fmaf(a.x, g.x, fmaf(a.y, g.y, fmaf(a.z, g.z, fmaf(a.w, g.w, s1))));
                s2 = fmaf(bb.x, g.x, fmaf(bb.y, g.y, fmaf(bb.z, g.z, fmaf(bb.w, g.w, s2))));
            }
            bt[(64 + n) * LDA + k] = __float2half_rn(s1);
            wfgb[n * 72 + k]       = __float2half_rn(s2);
        }
        if (tid < 64) {
            float s = bga[tid];
            const float* gt = sWgaT + tid * 68;
            for (int e = 0; e < 64; e++) s = fmaf(bphi[e] - bpsi[e], gt[e], s);
            cgs[tid] = s;
        }
        {
            int r = tid >> 6, d = tid & 63;
            float s;
            if (r < 3) {
                s = 0.f;
                for (int c = 0; c < 64; c++) s = fmaf(Wd1[r * 64 + c], Wd2[c * 64 + d], s);
            } else {
                s = bd2[d];
                for (int c = 0; c < 64; c++) s = fmaf(bd1[c], Wd2[c * 64 + d], s);
            }
            ((float*)(sm + MCVO))[tid] = s;
        }
        if (tid < 64) ((float*)(sm + BALO))[tid] = bal[tid];
        __syncthreads();
    }

    // ---- Phase A2: fgc = f@Wfg + cg -> staged in out[] ----
    {
        __half* anf = (__half*)(sm + AO);
        float*  fgD = (float*)(sm + ABO);
        for (int ch = 0; ch * 16 < numtt; ch++) {
            {
                const int r = tid >> 1, h = tid & 1;
                const int tt = ch * 16 + (r >> 3);
                long pt = -1;
                if (tt < numtt) {
                    long cand = (long)(bx + tt * G) * 8 + (r & 7);
                    if (cand < N) pt = cand;
                }
                #pragma unroll
                for (int i4 = 0; i4 < 8; i4++) {
                    const int c = h * 32 + i4 * 4;
                    float4 v = (pt >= 0) ? *(const float4*)(pfeat + pt * 64 + c)
                                         : make_float4(0.f, 0.f, 0.f, 0.f);
                    __half2 h0 = __floats2half2_rn(v.x, v.y);
                    __half2 h1 = __floats2half2_rn(v.z, v.w);
                    *(uint2*)(anf + r * LDA + c) = make_uint2(*(uint32_t*)&h0, *(uint32_t*)&h1);
                }
            }
            __syncthreads();
            {
                const int r2 = warp >> 1, c2 = warp & 1;
                wmma::fragment<wmma::matrix_b, 16, 16, 16, __half, wmma::col_major> bf[2][4];
                #pragma unroll
                for (int j = 0; j < 2; j++)
                    #pragma unroll
                    for (int kk = 0; kk < 4; kk++)
                        wmma::load_matrix_sync(bf[j][kk],
                            wfgb + (c2 * 2 + j) * 16 * 72 + kk * 16, 72);
                #pragma unroll
                for (int m = 0; m < 2; m++) {
                    const int mb = r2 * 2 + m;
                    wmma::fragment<wmma::matrix_a, 16, 16, 16, __half, wmma::row_major> af;
                    wmma::fragment<wmma::accumulator, 16, 16, 16, float> c0, c1a;
                    wmma::fill_fragment(c0, 0.f);
                    wmma::fill_fragment(c1a, 0.f);
                    #pragma unroll
                    for (int kk = 0; kk < 4; kk++) {
                        wmma::load_matrix_sync(af, anf + mb * 16 * LDA + kk * 16, LDA);
                        wmma::mma_sync(c0, af, bf[0][kk], c0);
                        wmma::mma_sync(c1a, af, bf[1][kk], c1a);
                    }
                    wmma::store_matrix_sync(fgD + mb * 16 * LDF + (c2 * 2 + 0) * 16, c0,
                                            LDF, wmma::mem_row_major);
                    wmma::store_matrix_sync(fgD + mb * 16 * LDF + (c2 * 2 + 1) * 16, c1a,
                                            LDF, wmma::mem_row_major);
                }
            }
            __syncthreads();
            #pragma unroll
            for (int m = 0; m < 32; m++) {
                int v = tid + 256 * m;
                int r = v >> 6, d = v & 63;
                int tt = ch * 16 + (r >> 3);
                if (tt < numtt) {
                    long pt = (long)(bx + tt * G) * 8 + (r & 7);
                    if (pt < N) out[pt * 64 + d] = fgD[r * LDF + d] + cgs[d];
                }
            }
            __syncthreads();
        }
    }

    // ---- persistent B fragments (registers, once) ----
    uint32_t Bf[8][8][2];
    {
        const int ng = cg * 64 + (lane >> 2);
        #pragma unroll
        for (int n8 = 0; n8 < 8; n8++)
            #pragma unroll
            for (int kk = 0; kk < 8; kk++) {
                const __half* src = bt + (ng + n8 * 8) * LDA + kk * 16 + 2 * (lane & 3);
                Bf[n8][kk][0] = *(const uint32_t*)src;
                Bf[n8][kk][1] = *(const uint32_t*)(src + 8);
            }
    }
    __syncthreads();

    // ---- Phase B ----
    const __half* Ah = (const __half*)(sm + AO);
    float* wb = (float*)(sm + WBO);
    float* ab = (float*)(sm + ABO);
    const float* fgcs = (const float*)(sm + FGCSO);
    const float* balv = (const float*)(sm + BALO);
    const uint32_t smA32 = s2u(sm + AO);

    int t = bx;
    if (t < ntiles) prefetch_tile(sm, t, tid, pxyz, nxyz, nfeat, out, N);

    for (; t < ntiles; t += G) {
        cp_wait<0>();
        __syncthreads();
        convert_tile(sm, tid);
        __syncthreads();
        if (t + G < ntiles) prefetch_tile(sm, t + G, tid, pxyz, nxyz, nfeat, out, N);

        #pragma unroll
        for (int mg = 0; mg < 2; mg++) {
            const int row0 = rg * 32 + mg * 16;
            const int p = rg * 2 + mg;
            const uint32_t abase =
                smA32 + (uint32_t)(((row0 + (lane & 15)) * LDA + (lane >> 4) * 8) * 2);

            float acc[8][4];
            #pragma unroll
            for (int n8 = 0; n8 < 8; n8++)
                acc[n8][0] = acc[n8][1] = acc[n8][2] = acc[n8][3] = 0.f;

            const int nkk = cg ? 8 : 4;
            for (int kk = 0; kk < nkk; kk++) {
                uint32_t a[4];
                ldmx4(a, abase + kk * 32);
                #pragma unroll
                for (int n8 = 0; n8 < 8; n8++) mma16816(acc[n8], a, Bf[n8][kk]);
            }

            const int rl = p * 16 + (lane >> 2);
            if (cg) {
                float slo = 0.f, shi = 0.f;
                #pragma unroll
                for (int n8 = 0; n8 < 8; n8++) {
                    const int d0 = n8 * 8 + 2 * (lane & 3);
                    float2 fg = *(const float2*)(fgcs + p * 64 + d0);
                    acc[n8][0] = __expf(fg.x - acc[n8][0]);
                    acc[n8][1] = __expf(fg.y - acc[n8][1]);
                    acc[n8][2] = __expf(fg.x - acc[n8][2]);
                    acc[n8][3] = __expf(fg.y - acc[n8][3]);
                    slo += acc[n8][0] + acc[n8][1];
                    shi += acc[n8][2] + acc[n8][3];
                }
                slo += __shfl_xor_sync(0xffffffffu, slo, 1);
                slo += __shfl_xor_sync(0xffffffffu, slo, 2);
                shi += __shfl_xor_sync(0xffffffffu, shi, 1);
                shi += __shfl_xor_sync(0xffffffffu, shi, 2);
                const float il = __fdividef(1.f, slo), ih = __fdividef(1.f, shi);
                #pragma unroll
                for (int n8 = 0; n8 < 8; n8++) {
                    const int d0 = n8 * 8 + 2 * (lane & 3);
                    *(float2*)(wb + rl * LDW + d0) =
                        make_float2(acc[n8][0] * il, acc[n8][1] * il);
                    *(float2*)(wb + (rl + 8) * LDW + d0) =
                        make_float2(acc[n8][2] * ih, acc[n8][3] * ih);
                }
            } else {
                #pragma unroll
                for (int n8 = 0; n8 < 8; n8++) {
                    const int d0 = n8 * 8 + 2 * (lane & 3);
                    float2 bl = *(const float2*)(balv + d0);
                    __half2 dl = *(const __half2*)(Ah + rl * LDA + 64 + d0);
                    __half2 dh = *(const __half2*)(Ah + (rl + 8) * LDA + 64 + d0);
                    float2 dlo = __half22float2(dl), dhi = __half22float2(dh);
                    *(float2*)(ab + rl * LDW + d0) =
                        make_float2(acc[n8][0] + bl.x + dlo.x, acc[n8][1] + bl.y + dlo.y);
                    *(float2*)(ab + (rl + 8) * LDW + d0) =
                        make_float2(acc[n8][2] + bl.x + dhi.x, acc[n8][3] + bl.y + dhi.y);
                }
            }
        }
        __syncthreads();

        // k-reduction
        #pragma unroll
        for (int m = 0; m < 2; m++) {
            int v = tid + 256 * m;
            int p = v >> 6, d = v & 63;
            const int r0 = p * 16;
            float s = 0.f;
            #pragma unroll
            for (int k = 0; k < 16; k++)
                s = fmaf(wb[(r0 + k) * LDW + d], ab[(r0 + k) * LDW + d], s);
            long gp = (long)t * 8 + p;
            if (gp < N) out[gp * 64 + d] = s;
        }
        __syncthreads();
    }
}

extern "C" void kernel_launch(void* const* d_in, const int* in_sizes, int n_in,
                              void* d_out, int out_size)
{
    const float* pxyz  = (const float*)d_in[0];
    const float* pfeat = (const float*)d_in[1];
    const float* nxyz  = (const float*)d_in[2];
    const float* nfeat = (const float*)d_in[3];
    const float* Wphi  = (const float*)d_in[4];
    const float* bphi  = (const float*)d_in[5];
    const float* Wpsi  = (const float*)d_in[6];
    const float* bpsi  = (const float*)d_in[7];
    const float* Wal   = (const float*)d_in[8];
    const float* bal   = (const float*)d_in[9];
    const float* Wga   = (const float*)d_in[10];
    const float* bga   = (const float*)d_in[11];
    const float* Wd1   = (const float*)d_in[12];
    const float* bd1   = (const float*)d_in[13];
    const float* Wd2   = (const float*)d_in[14];
    const float* bd2   = (const float*)d_in[15];

    const int N = in_sizes[1] / DIM;

    int dev = 0;
    cudaGetDevice(&dev);
    int nsm = 148;
    cudaDeviceGetAttribute(&nsm, cudaDevAttrMultiProcessorCount, dev);

    cudaFuncSetAttribute(pt_main, cudaFuncAttributeMaxDynamicSharedMemorySize, SMEM_BYTES);

    const int ntiles = (N + 7) >> 3;
    const int grid = (ntiles < nsm) ? ntiles : nsm;
    pt_main<<<grid, THREADS, SMEM_BYTES>>>(pxyz, pfeat, nxyz, nfeat,
                                           Wphi, bphi, Wpsi, bpsi, Wal, bal,
                                           Wga, bga, Wd1, bd1, Wd2, bd2,
                                           (float*)d_out, N);
}